// round 4
// baseline (speedup 1.0000x reference)
#include <cuda_runtime.h>
#include <cstdint>

#define FILLV (-1000.0f)
#define NEG_BIG (-3.0e38f)

// Per-batch scratch (allocation-free rule: __device__ globals).
__device__ float g_total[512];
__device__ float g_real[512];

// ---- f32x2 / b64 helpers -------------------------------------------------
__device__ __forceinline__ unsigned long long pk2(float x, float y) {
    unsigned long long r;
    asm("mov.b64 %0, {%1, %2};" : "=l"(r) : "f"(x), "f"(y));
    return r;
}
__device__ __forceinline__ void upk2(unsigned long long a, float& x, float& y) {
    asm("mov.b64 {%0, %1}, %2;" : "=f"(x), "=f"(y) : "l"(a));
}
__device__ __forceinline__ unsigned long long fma2(unsigned long long a,
                                                   unsigned long long b,
                                                   unsigned long long c) {
    unsigned long long r;
    asm("fma.rn.f32x2 %0, %1, %2, %3;" : "=l"(r) : "l"(a), "l"(b), "l"(c));
    return r;
}

// ---- forward (total path score) kernel -----------------------------------
// grid = 512 (one CTA per batch), block = 256.
// Thread t: column j = t & 127, row-half h = t >> 7 (rows h*64 .. h*64+63).
// Register-resident: T column slice (64 f32) + exp(T - colmax) slice (32 f32x2).
__global__ void __launch_bounds__(256, 1)
crf_forward_kernel(const float* __restrict__ em, const float* __restrict__ trans) {
    __shared__ ulonglong2 shpv[64];     // {pre[2m],pre[2m+1] | v[2m],v[2m+1]}
    __shared__ float spc[256];          // per-thread partial column max
    __shared__ float spw[256];          // per-thread partial matvec sum
    __shared__ float scol[128];         // colmax of transitions
    __shared__ float swS[4], swM[4];    // warp partials

    const int t = threadIdx.x;
    const int j = t & 127;
    const int h = t >> 7;
    const int b = blockIdx.x;
    const int rowbase = h * 64;

    // --- load T column slice, compute colmax, build Ep = exp(T - colmax) ---
    float Tc[64];
    float tcm = NEG_BIG;
#pragma unroll
    for (int k = 0; k < 64; ++k) {
        float tv = trans[(rowbase + k) * 128 + j];
        Tc[k] = tv;
        tcm = fmaxf(tcm, tv);
    }
    spc[t] = tcm;
    __syncthreads();
    if (t < 128) scol[t] = fmaxf(spc[t], spc[t + 128]);
    __syncthreads();
    const float colmax = scol[j];

    unsigned long long Ep[32];
#pragma unroll
    for (int k = 0; k < 32; ++k) {
        Ep[k] = pk2(expf(Tc[2 * k] - colmax), expf(Tc[2 * k + 1] - colmax));
    }

    // --- init state: pre = E[0] (0 at col 126, FILL elsewhere) ---
    if (t < 128) {
        float p  = (j == 126) ? 0.0f : FILLV;
        float vv = (j == 126) ? 1.0f : 0.0f;   // exp(pre - pmax), pmax = 0
        float* pvf = (float*)shpv;
        int m = j >> 1, lane = j & 1;
        pvf[m * 4 + lane]     = p;
        pvf[m * 4 + 2 + lane] = vv;
    }
    float pmax = 0.0f;
    float Lacc = 0.0f;
    float vkeep = 0.0f;
    __syncthreads();

    const float* emb = em + (size_t)b * 512 * 126;

    // obs for step s=1 (row 0 of emissions); FILL for j >= 126
    float obs_cur = FILLV;
    if (t < 128 && j < 126) obs_cur = emb[j];

    for (int s = 1; s <= 513; ++s) {
        // Prefetch next step's observation (hides DRAM latency behind phase 0).
        float obs_nxt;
        {
            const int sn = s + 1;
            if (sn <= 512) {
                obs_nxt = (t < 128 && j < 126) ? emb[(sn - 1) * 126 + j] : FILLV;
            } else {
                obs_nxt = (j == 127) ? 0.0f : FILLV;   // END pseudo-row
            }
        }

        // --- phase 0: max-plus + matvec over this thread's 64 rows ---
        float cm0 = NEG_BIG, cm1 = NEG_BIG;
        unsigned long long wacc = 0ULL;              // (0.0f, 0.0f)
        const ulonglong2* pvb = shpv + h * 32;
#pragma unroll
        for (int k = 0; k < 32; ++k) {
            ulonglong2 q = pvb[k];                   // LDS.128 broadcast
            float p0, p1;
            upk2(q.x, p0, p1);
            cm0 = fmaxf(cm0, p0 + Tc[2 * k]);
            cm1 = fmaxf(cm1, p1 + Tc[2 * k + 1]);
            wacc = fma2(q.y, Ep[k], wacc);           // packed f32x2 FMA
        }
        float w0, w1;
        upk2(wacc, w0, w1);
        spc[t] = fmaxf(cm0, cm1);
        spw[t] = w0 + w1;
        __syncthreads();

        // --- phase 1: combine halves, per-column contribution, reductions ---
        float pnew = NEG_BIG;
        if (t < 128) {
            float c = fmaxf(spc[j], spc[j + 128]);
            float w = spw[j] + spw[j + 128];
            float contrib = expf(pmax + colmax - c) * w;
            pnew = obs_cur + c;
            float sred = contrib, mred = pnew;
#pragma unroll
            for (int o = 16; o; o >>= 1) {
                sred += __shfl_xor_sync(0xffffffffu, sred, o);
                mred = fmaxf(mred, __shfl_xor_sync(0xffffffffu, mred, o));
            }
            if ((t & 31) == 0) { swS[t >> 5] = sred; swM[t >> 5] = mred; }
        }
        __syncthreads();

        // --- phase 2: scalar combine (redundant in all threads), new state ---
        float S = (swS[0] + swS[1]) + (swS[2] + swS[3]);
        float pmaxn = fmaxf(fmaxf(swM[0], swM[1]), fmaxf(swM[2], swM[3]));
        Lacc += logf(S);
        if (t < 128) {
            float vv = expf(pnew - pmaxn);
            vkeep = vv;
            float* pvf = (float*)shpv;
            int m = j >> 1, lane = j & 1;
            pvf[m * 4 + lane]     = pnew;
            pvf[m * 4 + 2 + lane] = vv;
        }
        pmax = pmaxn;
        __syncthreads();
        obs_cur = obs_nxt;
    }

    // --- final log-sum-exp: Sum of v (already exp(pre - pmax)) ---
    if (t < 128) {
        float sred = vkeep;
#pragma unroll
        for (int o = 16; o; o >>= 1) sred += __shfl_xor_sync(0xffffffffu, sred, o);
        if ((t & 31) == 0) swS[t >> 5] = sred;
    }
    __syncthreads();
    if (t == 0) {
        float Sf = (swS[0] + swS[1]) + (swS[2] + swS[3]);
        g_total[b] = pmax + logf(Sf) + Lacc;
    }
}

// ---- gold-path score kernel ----------------------------------------------
__global__ void crf_real_kernel(const float* __restrict__ em,
                                const int* __restrict__ labels,
                                const float* __restrict__ trans) {
    const int b = blockIdx.x;
    const int t = threadIdx.x;   // 128 threads
    __shared__ float sw[4];
    const int* lb = labels + b * 512;
    const float* emb = em + (size_t)b * 512 * 126;

    float acc = 0.0f;
    for (int tt = t; tt < 512; tt += 128) {
        int l0 = lb[tt];
        acc += emb[tt * 126 + l0];
        int l1 = (tt < 511) ? lb[tt + 1] : 127;     // END = L+1 = 127
        acc += trans[l0 * 128 + l1];
    }
    if (t == 0) acc += trans[126 * 128 + lb[0]];     // START = L = 126

#pragma unroll
    for (int o = 16; o; o >>= 1) acc += __shfl_xor_sync(0xffffffffu, acc, o);
    if ((t & 31) == 0) sw[t >> 5] = acc;
    __syncthreads();
    if (t == 0) g_real[b] = (sw[0] + sw[1]) + (sw[2] + sw[3]);
}

// ---- fixed-order final reduction (deterministic) -------------------------
__global__ void crf_reduce_kernel(float* __restrict__ out) {
    const int t = threadIdx.x;   // 512 threads
    __shared__ float sw[16];
    float d = g_total[t] - g_real[t];
#pragma unroll
    for (int o = 16; o; o >>= 1) d += __shfl_xor_sync(0xffffffffu, d, o);
    if ((t & 31) == 0) sw[t >> 5] = d;
    __syncthreads();
    if (t == 0) {
        float s = 0.0f;
#pragma unroll
        for (int w = 0; w < 16; ++w) s += sw[w];
        out[0] = s;
    }
}

extern "C" void kernel_launch(void* const* d_in, const int* in_sizes, int n_in,
                              void* d_out, int out_size) {
    const float* em     = (const float*)d_in[0];   // [512, 512, 126] f32
    const int*   labels = (const int*)d_in[1];     // [512, 512] i32
    const float* trans  = (const float*)d_in[2];   // [128, 128] f32

    crf_forward_kernel<<<512, 256>>>(em, trans);
    crf_real_kernel<<<512, 128>>>(em, labels, trans);
    crf_reduce_kernel<<<1, 512>>>((float*)d_out);
}

// round 6
// speedup vs baseline: 1.2852x; 1.2852x over previous
#include <cuda_runtime.h>
#include <cstdint>

#define FILLV (-1000.0f)
#define NEG_BIG (-3.0e38f)

// Per-batch scratch (allocation-free rule: __device__ globals).
__device__ float g_total[512];
__device__ float g_real[512];

// ---- f32x2 / b64 helpers -------------------------------------------------
__device__ __forceinline__ unsigned long long pk2(float x, float y) {
    unsigned long long r;
    asm("mov.b64 %0, {%1, %2};" : "=l"(r) : "f"(x), "f"(y));
    return r;
}
__device__ __forceinline__ void upk2(unsigned long long a, float& x, float& y) {
    asm("mov.b64 {%0, %1}, %2;" : "=f"(x), "=f"(y) : "l"(a));
}
__device__ __forceinline__ unsigned long long fma2(unsigned long long a,
                                                   unsigned long long b,
                                                   unsigned long long c) {
    unsigned long long r;
    asm("fma.rn.f32x2 %0, %1, %2, %3;" : "=l"(r) : "l"(a), "l"(b), "l"(c));
    return r;
}
__device__ __forceinline__ unsigned long long add2(unsigned long long a,
                                                   unsigned long long b) {
    unsigned long long r;
    asm("add.rn.f32x2 %0, %1, %2;" : "=l"(r) : "l"(a), "l"(b));
    return r;
}

// ---- forward (total path score) kernel -----------------------------------
// 4 batches per CTA. grid = 128 (1 full wave on 148 SMs), block = 256.
// Thread t: column jj = t & 127, row-half h = t >> 7 (rows h*64 .. h*64+63).
// Register-resident (shared across all 4 batches): packed T column slice
// Tc2[32] + packed exp(T - colmax) Ep[32].
// Phase 0: all threads process all 4 batches (4-way ILP).
// Phases 1/2: half h owns batches 2h and 2h+1 (halves run concurrently).
__global__ void __launch_bounds__(256, 1)
crf_forward_kernel(const float* __restrict__ em, const float* __restrict__ trans) {
    __shared__ ulonglong2 shpv[4][64];   // per batch: {pre[2m],pre[2m+1] | v[2m],v[2m+1]}
    __shared__ float spc[4][256];        // per batch: per-thread partial column max
    __shared__ float spw[4][256];        // per batch: per-thread partial matvec sum
    __shared__ float scol[128];          // colmax of transitions (batch-independent)
    __shared__ float swS[4][4], swM[4][4];

    const int t  = threadIdx.x;
    const int jj = t & 127;
    const int h  = t >> 7;
    const int b0 = blockIdx.x * 4;
    const int rowbase = h * 64;

    // --- load T column slice, compute colmax, build packed Tc2 / Ep ---
    float Tcs[64];
    float tcm = NEG_BIG;
#pragma unroll
    for (int k = 0; k < 64; ++k) {
        float tv = trans[(rowbase + k) * 128 + jj];
        Tcs[k] = tv;
        tcm = fmaxf(tcm, tv);
    }
    spc[0][t] = tcm;
    __syncthreads();
    if (t < 128) scol[t] = fmaxf(spc[0][t], spc[0][t + 128]);
    __syncthreads();
    const float colmax = scol[jj];

    unsigned long long Tc2[32], Ep[32];
#pragma unroll
    for (int k = 0; k < 32; ++k) {
        Tc2[k] = pk2(Tcs[2 * k], Tcs[2 * k + 1]);
        Ep[k]  = pk2(expf(Tcs[2 * k] - colmax), expf(Tcs[2 * k + 1] - colmax));
    }

    // --- init state for the 2 batches this half owns (and mirrors) ---
    {
        float p  = (jj == 126) ? 0.0f : FILLV;
        float vv = (jj == 126) ? 1.0f : 0.0f;
        int m = jj >> 1, lane = jj & 1;
        float* pvf0 = (float*)shpv[2 * h];
        float* pvf1 = (float*)shpv[2 * h + 1];
        pvf0[m * 4 + lane] = p;  pvf0[m * 4 + 2 + lane] = vv;
        pvf1[m * 4 + lane] = p;  pvf1[m * 4 + 2 + lane] = vv;
    }
    float pmax0 = 0.0f, pmax1 = 0.0f;
    float Lacc0 = 0.0f, Lacc1 = 0.0f;
    float vkeep0 = 0.0f, vkeep1 = 0.0f;
    __syncthreads();

    const float* embp0 = em + (size_t)(b0 + 2 * h) * 512 * 126;
    const float* embp1 = embp0 + 512 * 126;

    // obs for step s=1 (emissions row 0), owned batches only
    float obs_c0 = (jj < 126) ? embp0[jj] : FILLV;
    float obs_c1 = (jj < 126) ? embp1[jj] : FILLV;

    const ulonglong2* const pvA = shpv[0] + h * 32;
    const ulonglong2* const pvB = shpv[1] + h * 32;
    const ulonglong2* const pvC = shpv[2] + h * 32;
    const ulonglong2* const pvD = shpv[3] + h * 32;

    for (int s = 1; s <= 513; ++s) {
        // Prefetch next step's observations (hidden behind phase 0).
        float obs_n0, obs_n1;
        {
            const int sn = s + 1;
            if (sn <= 512) {
                obs_n0 = (jj < 126) ? embp0[(size_t)s * 126 + jj] : FILLV;
                obs_n1 = (jj < 126) ? embp1[(size_t)s * 126 + jj] : FILLV;
            } else {
                float v = (jj == 127) ? 0.0f : FILLV;  // END pseudo-row
                obs_n0 = v; obs_n1 = v;
            }
        }

        // --- phase 0: max-plus + matvec over this thread's 64 rows, 4 batches ---
        float cm0A = NEG_BIG, cm1A = NEG_BIG;
        float cm0B = NEG_BIG, cm1B = NEG_BIG;
        float cm0C = NEG_BIG, cm1C = NEG_BIG;
        float cm0D = NEG_BIG, cm1D = NEG_BIG;
        unsigned long long wA = 0ULL, wB = 0ULL, wC = 0ULL, wD = 0ULL;
#pragma unroll
        for (int k = 0; k < 32; ++k) {
            ulonglong2 qA = pvA[k];
            ulonglong2 qB = pvB[k];
            ulonglong2 qC = pvC[k];
            ulonglong2 qD = pvD[k];
            float s0, s1;
            unsigned long long u;
            u = add2(qA.x, Tc2[k]); upk2(u, s0, s1);
            cm0A = fmaxf(cm0A, s0); cm1A = fmaxf(cm1A, s1);
            wA = fma2(qA.y, Ep[k], wA);
            u = add2(qB.x, Tc2[k]); upk2(u, s0, s1);
            cm0B = fmaxf(cm0B, s0); cm1B = fmaxf(cm1B, s1);
            wB = fma2(qB.y, Ep[k], wB);
            u = add2(qC.x, Tc2[k]); upk2(u, s0, s1);
            cm0C = fmaxf(cm0C, s0); cm1C = fmaxf(cm1C, s1);
            wC = fma2(qC.y, Ep[k], wC);
            u = add2(qD.x, Tc2[k]); upk2(u, s0, s1);
            cm0D = fmaxf(cm0D, s0); cm1D = fmaxf(cm1D, s1);
            wD = fma2(qD.y, Ep[k], wD);
        }
        {
            float w0, w1;
            upk2(wA, w0, w1); spc[0][t] = fmaxf(cm0A, cm1A); spw[0][t] = w0 + w1;
            upk2(wB, w0, w1); spc[1][t] = fmaxf(cm0B, cm1B); spw[1][t] = w0 + w1;
            upk2(wC, w0, w1); spc[2][t] = fmaxf(cm0C, cm1C); spw[2][t] = w0 + w1;
            upk2(wD, w0, w1); spc[3][t] = fmaxf(cm0D, cm1D); spw[3][t] = w0 + w1;
        }
        __syncthreads();

        // --- phase 1: half h combines + reduces its 2 owned batches ---
        const int g0 = 2 * h, g1 = g0 + 1;
        float pnew0, pnew1;
        {
            float c0 = fmaxf(spc[g0][jj], spc[g0][128 + jj]);
            float w0 = spw[g0][jj] + spw[g0][128 + jj];
            float contrib0 = expf(pmax0 + colmax - c0) * w0;
            pnew0 = obs_c0 + c0;
            float c1 = fmaxf(spc[g1][jj], spc[g1][128 + jj]);
            float w1 = spw[g1][jj] + spw[g1][128 + jj];
            float contrib1 = expf(pmax1 + colmax - c1) * w1;
            pnew1 = obs_c1 + c1;

            float sr0 = contrib0, mr0 = pnew0;
            float sr1 = contrib1, mr1 = pnew1;
#pragma unroll
            for (int o = 16; o; o >>= 1) {
                sr0 += __shfl_xor_sync(0xffffffffu, sr0, o);
                mr0 = fmaxf(mr0, __shfl_xor_sync(0xffffffffu, mr0, o));
                sr1 += __shfl_xor_sync(0xffffffffu, sr1, o);
                mr1 = fmaxf(mr1, __shfl_xor_sync(0xffffffffu, mr1, o));
            }
            if ((t & 31) == 0) {
                const int wi = (t >> 5) & 3;
                swS[g0][wi] = sr0; swM[g0][wi] = mr0;
                swS[g1][wi] = sr1; swM[g1][wi] = mr1;
            }
        }
        // half-scoped barrier (ids 1 and 2) — only this half reads swS/swM[g0,g1]
        asm volatile("bar.sync %0, 128;" :: "r"(h + 1) : "memory");

        // --- phase 2: scalar combine + publish new state for owned batches ---
        {
            float S0 = (swS[g0][0] + swS[g0][1]) + (swS[g0][2] + swS[g0][3]);
            float S1 = (swS[g1][0] + swS[g1][1]) + (swS[g1][2] + swS[g1][3]);
            float pm0 = fmaxf(fmaxf(swM[g0][0], swM[g0][1]), fmaxf(swM[g0][2], swM[g0][3]));
            float pm1 = fmaxf(fmaxf(swM[g1][0], swM[g1][1]), fmaxf(swM[g1][2], swM[g1][3]));
            Lacc0 += logf(S0);
            Lacc1 += logf(S1);
            float vv0 = expf(pnew0 - pm0);
            float vv1 = expf(pnew1 - pm1);
            vkeep0 = vv0; vkeep1 = vv1;
            int m = jj >> 1, lane = jj & 1;
            float* pvf0 = (float*)shpv[g0];
            float* pvf1 = (float*)shpv[g1];
            pvf0[m * 4 + lane] = pnew0;  pvf0[m * 4 + 2 + lane] = vv0;
            pvf1[m * 4 + lane] = pnew1;  pvf1[m * 4 + 2 + lane] = vv1;
            pmax0 = pm0; pmax1 = pm1;
        }
        __syncthreads();
        obs_c0 = obs_n0;
        obs_c1 = obs_n1;
    }

    // --- final log-sum-exp per owned batch ---
    {
        float sr0 = vkeep0, sr1 = vkeep1;
#pragma unroll
        for (int o = 16; o; o >>= 1) {
            sr0 += __shfl_xor_sync(0xffffffffu, sr0, o);
            sr1 += __shfl_xor_sync(0xffffffffu, sr1, o);
        }
        if ((t & 31) == 0) {
            const int wi = (t >> 5) & 3;
            swS[2 * h][wi] = sr0;
            swS[2 * h + 1][wi] = sr1;
        }
    }
    asm volatile("bar.sync %0, 128;" :: "r"(h + 1) : "memory");
    if (jj == 0) {
        const int g0 = 2 * h, g1 = g0 + 1;
        float Sf0 = (swS[g0][0] + swS[g0][1]) + (swS[g0][2] + swS[g0][3]);
        float Sf1 = (swS[g1][0] + swS[g1][1]) + (swS[g1][2] + swS[g1][3]);
        g_total[b0 + g0] = pmax0 + logf(Sf0) + Lacc0;
        g_total[b0 + g1] = pmax1 + logf(Sf1) + Lacc1;
    }
}

// ---- gold-path score kernel ----------------------------------------------
__global__ void crf_real_kernel(const float* __restrict__ em,
                                const int* __restrict__ labels,
                                const float* __restrict__ trans) {
    const int b = blockIdx.x;
    const int t = threadIdx.x;   // 128 threads
    __shared__ float sw[4];
    const int* lb = labels + b * 512;
    const float* emb = em + (size_t)b * 512 * 126;

    float acc = 0.0f;
    for (int tt = t; tt < 512; tt += 128) {
        int l0 = lb[tt];
        acc += emb[tt * 126 + l0];
        int l1 = (tt < 511) ? lb[tt + 1] : 127;     // END = L+1 = 127
        acc += trans[l0 * 128 + l1];
    }
    if (t == 0) acc += trans[126 * 128 + lb[0]];     // START = L = 126

#pragma unroll
    for (int o = 16; o; o >>= 1) acc += __shfl_xor_sync(0xffffffffu, acc, o);
    if ((t & 31) == 0) sw[t >> 5] = acc;
    __syncthreads();
    if (t == 0) g_real[b] = (sw[0] + sw[1]) + (sw[2] + sw[3]);
}

// ---- fixed-order final reduction (deterministic) -------------------------
__global__ void crf_reduce_kernel(float* __restrict__ out) {
    const int t = threadIdx.x;   // 512 threads
    __shared__ float sw[16];
    float d = g_total[t] - g_real[t];
#pragma unroll
    for (int o = 16; o; o >>= 1) d += __shfl_xor_sync(0xffffffffu, d, o);
    if ((t & 31) == 0) sw[t >> 5] = d;
    __syncthreads();
    if (t == 0) {
        float s = 0.0f;
#pragma unroll
        for (int w = 0; w < 16; ++w) s += sw[w];
        out[0] = s;
    }
}

extern "C" void kernel_launch(void* const* d_in, const int* in_sizes, int n_in,
                              void* d_out, int out_size) {
    const float* em     = (const float*)d_in[0];   // [512, 512, 126] f32
    const int*   labels = (const int*)d_in[1];     // [512, 512] i32
    const float* trans  = (const float*)d_in[2];   // [128, 128] f32

    crf_forward_kernel<<<128, 256>>>(em, trans);
    crf_real_kernel<<<512, 128>>>(em, labels, trans);
    crf_reduce_kernel<<<1, 512>>>((float*)d_out);
}